// round 1
// baseline (speedup 1.0000x reference)
#include <cuda_runtime.h>
#include <math.h>

#define D_MODEL     1024
#define EXPERT_DIM  2048
#define NUM_EXPERTS 16
#define SEQ_LEN     2048
#define BATCH       2
#define NTOK        (SEQ_LEN*BATCH)      // 4096 tokens
#define NASSIGN     (NTOK*2)             // 8192 (token, k) assignments

// ---- scratch (static __device__: no allocations allowed) ----
__device__ float g_H[(size_t)NASSIGN * EXPERT_DIM];   // 64 MB: relu(x@W1+b1) per assignment
__device__ float g_Y[(size_t)NASSIGN * D_MODEL];      // 32 MB: w * (h@W2+b2) per assignment
__device__ int   g_cnt[NUM_EXPERTS];
__device__ int   g_list[NUM_EXPERTS * NTOK];          // packed entry = token*2 + kslot
__device__ float g_rw[NASSIGN];                       // gate weight per (token, kslot)

__global__ void zero_cnt_kernel() {
    if (threadIdx.x < NUM_EXPERTS) g_cnt[threadIdx.x] = 0;
}

// ---- gating: one warp per token ----
__global__ void gate_kernel(const float* __restrict__ x,
                            const float* __restrict__ Wg,
                            const float* __restrict__ bg,
                            const float* __restrict__ bias) {
    int gwarp = (blockIdx.x * blockDim.x + threadIdx.x) >> 5;
    int lane  = threadIdx.x & 31;
    if (gwarp >= NTOK) return;
    const float* xr = x + (size_t)gwarp * D_MODEL;

    float xv[32];
    #pragma unroll
    for (int j = 0; j < 32; j++) xv[j] = xr[lane + 32 * j];

    float logits[NUM_EXPERTS];
    #pragma unroll
    for (int e = 0; e < NUM_EXPERTS; e++) {
        float s = 0.f;
        #pragma unroll
        for (int j = 0; j < 32; j++)
            s += xv[j] * Wg[(size_t)(lane + 32 * j) * NUM_EXPERTS + e];
        #pragma unroll
        for (int o = 16; o; o >>= 1) s += __shfl_xor_sync(0xffffffffu, s, o);
        logits[e] = s + bg[e] + bias[e];
    }

    if (lane == 0) {
        // top-1 (lowest index wins ties, matching jax top_k)
        int e0 = 0; float v0 = logits[0];
        #pragma unroll
        for (int e = 1; e < NUM_EXPERTS; e++)
            if (logits[e] > v0) { v0 = logits[e]; e0 = e; }
        // top-2
        int e1 = -1; float v1 = -1e30f;
        #pragma unroll
        for (int e = 0; e < NUM_EXPERTS; e++)
            if (e != e0 && logits[e] > v1) { v1 = logits[e]; e1 = e; }

        // softmax over the two top values (max-subtracted)
        float ew1 = __expf(v1 - v0);
        float inv = 1.f / (1.f + ew1);
        float w0 = inv, w1 = ew1 * inv;

        g_rw[gwarp * 2 + 0] = w0;
        g_rw[gwarp * 2 + 1] = w1;
        int p0 = atomicAdd(&g_cnt[e0], 1);
        g_list[e0 * NTOK + p0] = gwarp * 2 + 0;
        int p1 = atomicAdd(&g_cnt[e1], 1);
        g_list[e1 * NTOK + p1] = gwarp * 2 + 1;
    }
}

// ---- grouped expert GEMM: 64x64 tile, 256 threads, 4x4 per thread ----
// FC1: A = x rows gathered by token, K=1024, N=2048, out = relu(.+b1) -> g_H
// FC2: A = g_H rows per assignment,  K=2048, N=1024, out = w*(.+b2)  -> g_Y
template<int K, int N, bool FC1>
__global__ __launch_bounds__(256)
void expert_gemm(const float* __restrict__ Xbase,
                 const float* __restrict__ Wbase,
                 const float* __restrict__ BiasBase) {
    const int e   = blockIdx.z;
    const int cnt = g_cnt[e];
    const int m0  = blockIdx.x * 64;
    if (m0 >= cnt) return;
    const int n0  = blockIdx.y * 64;

    const float* W  = Wbase   + (size_t)e * K * N;
    const float* bv = BiasBase + (size_t)e * N;

    __shared__ int   s_entry[64];
    __shared__ float As[16][68];
    __shared__ float Bs[16][68];

    const int tid = threadIdx.x;
    if (tid < 64) {
        int idx = m0 + tid;
        s_entry[tid] = (idx < cnt) ? g_list[e * NTOK + idx] : -1;
    }
    __syncthreads();

    // A-load mapping: each thread loads float4 for one m-row
    const int am = tid >> 2;            // 0..63
    const int ak = (tid & 3) * 4;       // 0,4,8,12
    const int entryA = s_entry[am];
    const float* arow = nullptr;
    if (entryA >= 0) {
        arow = FC1 ? (Xbase + (size_t)(entryA >> 1) * D_MODEL)
                   : (g_H  + (size_t)entryA * EXPERT_DIM);
    }
    // B-load mapping
    const int bk = tid >> 4;            // 0..15
    const int bn = (tid & 15) * 4;      // 0..60

    const int tx = tid & 15;
    const int ty = tid >> 4;

    float acc[4][4] = {};

    for (int k0 = 0; k0 < K; k0 += 16) {
        float4 av = make_float4(0.f, 0.f, 0.f, 0.f);
        if (arow) av = *(const float4*)(arow + k0 + ak);
        float4 bvv = *(const float4*)(W + (size_t)(k0 + bk) * N + n0 + bn);

        __syncthreads();
        As[ak + 0][am] = av.x; As[ak + 1][am] = av.y;
        As[ak + 2][am] = av.z; As[ak + 3][am] = av.w;
        *(float4*)&Bs[bk][bn] = bvv;
        __syncthreads();

        #pragma unroll
        for (int k = 0; k < 16; k++) {
            float4 a4 = *(const float4*)&As[k][ty * 4];
            float4 b4 = *(const float4*)&Bs[k][tx * 4];
            float a[4] = {a4.x, a4.y, a4.z, a4.w};
            float b[4] = {b4.x, b4.y, b4.z, b4.w};
            #pragma unroll
            for (int i = 0; i < 4; i++)
                #pragma unroll
                for (int j = 0; j < 4; j++)
                    acc[i][j] += a[i] * b[j];
        }
    }

    #pragma unroll
    for (int i = 0; i < 4; i++) {
        int m = ty * 4 + i;
        int entry = s_entry[m];
        if (entry < 0) continue;
        if (FC1) {
            float* orow = g_H + (size_t)entry * EXPERT_DIM + n0 + tx * 4;
            #pragma unroll
            for (int j = 0; j < 4; j++) {
                float v = acc[i][j] + bv[n0 + tx * 4 + j];
                orow[j] = v > 0.f ? v : 0.f;
            }
        } else {
            float w = g_rw[entry];
            float* orow = g_Y + (size_t)entry * D_MODEL + n0 + tx * 4;
            #pragma unroll
            for (int j = 0; j < 4; j++) {
                float v = acc[i][j] + bv[n0 + tx * 4 + j];
                orow[j] = w * v;
            }
        }
    }
}

// ---- combine: out[t] = Y[t, slot0] + Y[t, slot1] ----
__global__ void combine_kernel(float* __restrict__ out) {
    int idx = blockIdx.x * blockDim.x + threadIdx.x;   // over NTOK * D_MODEL/4
    if (idx >= NTOK * (D_MODEL / 4)) return;
    int t = idx / (D_MODEL / 4);
    int c = idx % (D_MODEL / 4);
    const float4* Y4 = (const float4*)g_Y;
    float4 a = Y4[(size_t)(2 * t + 0) * (D_MODEL / 4) + c];
    float4 b = Y4[(size_t)(2 * t + 1) * (D_MODEL / 4) + c];
    ((float4*)out)[idx] = make_float4(a.x + b.x, a.y + b.y, a.z + b.z, a.w + b.w);
}

extern "C" void kernel_launch(void* const* d_in, const int* in_sizes, int n_in,
                              void* d_out, int out_size) {
    (void)in_sizes; (void)n_in; (void)out_size;
    const float* x    = (const float*)d_in[0];
    const float* Wg   = (const float*)d_in[1];
    const float* bg   = (const float*)d_in[2];
    const float* bias = (const float*)d_in[3];
    const float* W1   = (const float*)d_in[4];
    const float* b1   = (const float*)d_in[5];
    const float* W2   = (const float*)d_in[6];
    const float* b2   = (const float*)d_in[7];
    float* out = (float*)d_out;

    zero_cnt_kernel<<<1, 32>>>();
    gate_kernel<<<NTOK / 8, 256>>>(x, Wg, bg, bias);
    // FC1: grid (m-tiles fastest for L2 weight reuse, n-tiles, experts)
    expert_gemm<D_MODEL, EXPERT_DIM, true><<<dim3(NTOK / 64, EXPERT_DIM / 64, NUM_EXPERTS), 256>>>(x, W1, b1);
    // FC2
    expert_gemm<EXPERT_DIM, D_MODEL, false><<<dim3(NTOK / 64, D_MODEL / 64, NUM_EXPERTS), 256>>>(x, W2, b2);
    combine_kernel<<<(NTOK * (D_MODEL / 4) + 255) / 256, 256>>>(out);
}

// round 2
// speedup vs baseline: 2.0472x; 2.0472x over previous
#include <cuda_runtime.h>
#include <stdint.h>
#include <math.h>

#define D_MODEL     1024
#define EXPERT_DIM  2048
#define NUM_EXPERTS 16
#define SEQ_LEN     2048
#define BATCH       2
#define NTOK        (SEQ_LEN*BATCH)      // 4096 tokens
#define NASSIGN     (NTOK*2)             // 8192 (token, k) assignments

// ---- scratch (static __device__: no allocations allowed) ----
__device__ float g_H[(size_t)NASSIGN * EXPERT_DIM];   // 64 MB: relu(x@W1+b1) per assignment
__device__ float g_Y[(size_t)NASSIGN * D_MODEL];      // 32 MB: w * (h@W2+b2) per assignment
__device__ int   g_cnt[NUM_EXPERTS];
__device__ int   g_list[NUM_EXPERTS * NTOK];          // packed entry = token*2 + kslot
__device__ float g_rw[NASSIGN];                       // gate weight per (token, kslot)

__global__ void zero_cnt_kernel() {
    if (threadIdx.x < NUM_EXPERTS) g_cnt[threadIdx.x] = 0;
}

// ---- gating: one warp per token ----
__global__ void gate_kernel(const float* __restrict__ x,
                            const float* __restrict__ Wg,
                            const float* __restrict__ bg,
                            const float* __restrict__ bias) {
    int gwarp = (blockIdx.x * blockDim.x + threadIdx.x) >> 5;
    int lane  = threadIdx.x & 31;
    if (gwarp >= NTOK) return;
    const float* xr = x + (size_t)gwarp * D_MODEL;

    float xv[32];
    #pragma unroll
    for (int j = 0; j < 32; j++) xv[j] = xr[lane + 32 * j];

    float logits[NUM_EXPERTS];
    #pragma unroll
    for (int e = 0; e < NUM_EXPERTS; e++) {
        float s = 0.f;
        #pragma unroll
        for (int j = 0; j < 32; j++)
            s += xv[j] * Wg[(size_t)(lane + 32 * j) * NUM_EXPERTS + e];
        #pragma unroll
        for (int o = 16; o; o >>= 1) s += __shfl_xor_sync(0xffffffffu, s, o);
        logits[e] = s + bg[e] + bias[e];
    }

    if (lane == 0) {
        int e0 = 0; float v0 = logits[0];
        #pragma unroll
        for (int e = 1; e < NUM_EXPERTS; e++)
            if (logits[e] > v0) { v0 = logits[e]; e0 = e; }
        int e1 = -1; float v1 = -1e30f;
        #pragma unroll
        for (int e = 0; e < NUM_EXPERTS; e++)
            if (e != e0 && logits[e] > v1) { v1 = logits[e]; e1 = e; }

        float ew1 = __expf(v1 - v0);
        float inv = 1.f / (1.f + ew1);
        g_rw[gwarp * 2 + 0] = inv;
        g_rw[gwarp * 2 + 1] = ew1 * inv;
        int p0 = atomicAdd(&g_cnt[e0], 1);
        g_list[e0 * NTOK + p0] = gwarp * 2 + 0;
        int p1 = atomicAdd(&g_cnt[e1], 1);
        g_list[e1 * NTOK + p1] = gwarp * 2 + 1;
    }
}

__device__ __forceinline__ uint32_t f2tf32(float f) {
    uint32_t r;
    asm("cvt.rna.tf32.f32 %0, %1;" : "=r"(r) : "f"(f));
    return r;
}

__device__ __forceinline__ void mma_tf32(float* d, const uint32_t* a, const uint32_t* b) {
    asm volatile(
        "mma.sync.aligned.m16n8k8.row.col.f32.tf32.tf32.f32 "
        "{%0,%1,%2,%3}, {%4,%5,%6,%7}, {%8,%9}, {%0,%1,%2,%3};\n"
        : "+f"(d[0]), "+f"(d[1]), "+f"(d[2]), "+f"(d[3])
        : "r"(a[0]), "r"(a[1]), "r"(a[2]), "r"(a[3]), "r"(b[0]), "r"(b[1]));
}

// ---- grouped expert GEMM on tensor cores (tf32 mma.sync) ----
// Block tile 128x128, 256 threads = 8 warps (4m x 2n), warp tile 32x64.
// K-step 16, double-buffered smem, stride 136 (conflict-free frag LDS/STS).
#define SSTR 136

template<int K, int N, bool FC1>
__global__ __launch_bounds__(256)
void expert_mma(const float* __restrict__ Xbase,
                const float* __restrict__ Wbase,
                const float* __restrict__ BiasBase) {
    const int e   = blockIdx.z;
    const int cnt = g_cnt[e];
    const int m0  = blockIdx.y * 128;
    if (m0 >= cnt) return;
    const int n0  = blockIdx.x * 128;

    const float* W  = Wbase    + (size_t)e * K * N;
    const float* bv = BiasBase + (size_t)e * N;

    __shared__ int      s_entry[128];
    __shared__ uint32_t As[2][16 * SSTR];
    __shared__ uint32_t Bs[2][16 * SSTR];

    const int tid = threadIdx.x;
    if (tid < 128) {
        int idx = m0 + tid;
        s_entry[tid] = (idx < cnt) ? g_list[e * NTOK + idx] : -1;
    }
    __syncthreads();

    // --- loader mappings ---
    const int am  = tid & 127;           // A row within tile
    const int akq = (tid >> 7) * 4;      // 0 or 4 (pairs: akq, akq+8)
    const int bc  = (tid & 31) * 4;      // B column (float4)
    const int br  = tid >> 5;            // B k-row (pairs: br, br+8)

    const float* a_row = nullptr;
    {
        int entry = s_entry[am];
        if (entry >= 0)
            a_row = FC1 ? (Xbase + (size_t)(entry >> 1) * D_MODEL)
                        : (g_H  + (size_t)entry * EXPERT_DIM);
    }

    // --- compute mappings ---
    const int lane = tid & 31;
    const int wm   = (tid >> 5) & 3;     // warp m index (0..3)
    const int wn   = tid >> 7;           // warp n index (0..1)
    const int m0w  = wm * 32;
    const int n0w  = wn * 64;
    const int qr   = lane >> 2;          // 0..7
    const int qc   = lane & 3;           // 0..3

    float acc[2][8][4];
    #pragma unroll
    for (int mi = 0; mi < 2; mi++)
        #pragma unroll
        for (int ni = 0; ni < 8; ni++)
            #pragma unroll
            for (int j = 0; j < 4; j++) acc[mi][ni][j] = 0.f;

    float4 av0, av1, bw0, bw1;

    // prologue load for k0 = 0
    {
        av0 = av1 = make_float4(0.f, 0.f, 0.f, 0.f);
        if (a_row) {
            av0 = *(const float4*)(a_row + akq);
            av1 = *(const float4*)(a_row + akq + 8);
        }
        bw0 = *(const float4*)(W + (size_t)br * N + n0 + bc);
        bw1 = *(const float4*)(W + (size_t)(br + 8) * N + n0 + bc);
    }

    int buf = 0;
    // store k0=0 into buf 0
    {
        As[buf][(akq + 0) * SSTR + am] = f2tf32(av0.x);
        As[buf][(akq + 1) * SSTR + am] = f2tf32(av0.y);
        As[buf][(akq + 2) * SSTR + am] = f2tf32(av0.z);
        As[buf][(akq + 3) * SSTR + am] = f2tf32(av0.w);
        As[buf][(akq + 8) * SSTR + am] = f2tf32(av1.x);
        As[buf][(akq + 9) * SSTR + am] = f2tf32(av1.y);
        As[buf][(akq +10) * SSTR + am] = f2tf32(av1.z);
        As[buf][(akq +11) * SSTR + am] = f2tf32(av1.w);
        uint4 p0 = make_uint4(f2tf32(bw0.x), f2tf32(bw0.y), f2tf32(bw0.z), f2tf32(bw0.w));
        uint4 p1 = make_uint4(f2tf32(bw1.x), f2tf32(bw1.y), f2tf32(bw1.z), f2tf32(bw1.w));
        *(uint4*)&Bs[buf][br * SSTR + bc]       = p0;
        *(uint4*)&Bs[buf][(br + 8) * SSTR + bc] = p1;
    }
    __syncthreads();

    for (int k0 = 0; k0 < K; k0 += 16) {
        const bool more = (k0 + 16) < K;
        if (more) {
            av0 = av1 = make_float4(0.f, 0.f, 0.f, 0.f);
            if (a_row) {
                av0 = *(const float4*)(a_row + k0 + 16 + akq);
                av1 = *(const float4*)(a_row + k0 + 16 + akq + 8);
            }
            bw0 = *(const float4*)(W + (size_t)(k0 + 16 + br) * N + n0 + bc);
            bw1 = *(const float4*)(W + (size_t)(k0 + 16 + br + 8) * N + n0 + bc);
        }

        // compute on current buffer: two k8 slices
        #pragma unroll
        for (int kk = 0; kk < 2; kk++) {
            const uint32_t* Ab = &As[buf][0];
            const uint32_t* Bb = &Bs[buf][0];
            int r0 = (kk * 8 + qc) * SSTR;
            int r4 = (kk * 8 + qc + 4) * SSTR;

            uint32_t afrag[2][4];
            #pragma unroll
            for (int mi = 0; mi < 2; mi++) {
                int mb = m0w + mi * 16 + qr;
                afrag[mi][0] = Ab[r0 + mb];
                afrag[mi][1] = Ab[r0 + mb + 8];
                afrag[mi][2] = Ab[r4 + mb];
                afrag[mi][3] = Ab[r4 + mb + 8];
            }
            uint32_t bfrag[8][2];
            #pragma unroll
            for (int ni = 0; ni < 8; ni++) {
                int nb = n0w + ni * 8 + qr;
                bfrag[ni][0] = Bb[r0 + nb];
                bfrag[ni][1] = Bb[r4 + nb];
            }
            #pragma unroll
            for (int mi = 0; mi < 2; mi++)
                #pragma unroll
                for (int ni = 0; ni < 8; ni++)
                    mma_tf32(acc[mi][ni], afrag[mi], bfrag[ni]);
        }

        if (more) {
            int nb = buf ^ 1;
            As[nb][(akq + 0) * SSTR + am] = f2tf32(av0.x);
            As[nb][(akq + 1) * SSTR + am] = f2tf32(av0.y);
            As[nb][(akq + 2) * SSTR + am] = f2tf32(av0.z);
            As[nb][(akq + 3) * SSTR + am] = f2tf32(av0.w);
            As[nb][(akq + 8) * SSTR + am] = f2tf32(av1.x);
            As[nb][(akq + 9) * SSTR + am] = f2tf32(av1.y);
            As[nb][(akq +10) * SSTR + am] = f2tf32(av1.z);
            As[nb][(akq +11) * SSTR + am] = f2tf32(av1.w);
            uint4 p0 = make_uint4(f2tf32(bw0.x), f2tf32(bw0.y), f2tf32(bw0.z), f2tf32(bw0.w));
            uint4 p1 = make_uint4(f2tf32(bw1.x), f2tf32(bw1.y), f2tf32(bw1.z), f2tf32(bw1.w));
            *(uint4*)&Bs[nb][br * SSTR + bc]       = p0;
            *(uint4*)&Bs[nb][(br + 8) * SSTR + bc] = p1;
        }
        __syncthreads();
        buf ^= 1;
    }

    // ---- epilogue ----
    #pragma unroll
    for (int mi = 0; mi < 2; mi++) {
        int r0 = m0w + mi * 16 + qr;
        int r1 = r0 + 8;
        int e0 = s_entry[r0];
        int e1 = s_entry[r1];
        #pragma unroll
        for (int ni = 0; ni < 8; ni++) {
            int ncol = n0 + n0w + ni * 8 + qc * 2;
            float bx = bv[ncol], by = bv[ncol + 1];
            if (FC1) {
                if (e0 >= 0) {
                    float* p = g_H + (size_t)e0 * EXPERT_DIM + ncol;
                    float v0 = acc[mi][ni][0] + bx;
                    float v1 = acc[mi][ni][1] + by;
                    *(float2*)p = make_float2(v0 > 0.f ? v0 : 0.f, v1 > 0.f ? v1 : 0.f);
                }
                if (e1 >= 0) {
                    float* p = g_H + (size_t)e1 * EXPERT_DIM + ncol;
                    float v0 = acc[mi][ni][2] + bx;
                    float v1 = acc[mi][ni][3] + by;
                    *(float2*)p = make_float2(v0 > 0.f ? v0 : 0.f, v1 > 0.f ? v1 : 0.f);
                }
            } else {
                if (e0 >= 0) {
                    float w = g_rw[e0];
                    float* p = g_Y + (size_t)e0 * D_MODEL + ncol;
                    *(float2*)p = make_float2(w * (acc[mi][ni][0] + bx),
                                              w * (acc[mi][ni][1] + by));
                }
                if (e1 >= 0) {
                    float w = g_rw[e1];
                    float* p = g_Y + (size_t)e1 * D_MODEL + ncol;
                    *(float2*)p = make_float2(w * (acc[mi][ni][2] + bx),
                                              w * (acc[mi][ni][3] + by));
                }
            }
        }
    }
}

// ---- combine: out[t] = Y[t, slot0] + Y[t, slot1] ----
__global__ void combine_kernel(float* __restrict__ out) {
    int idx = blockIdx.x * blockDim.x + threadIdx.x;
    if (idx >= NTOK * (D_MODEL / 4)) return;
    int t = idx / (D_MODEL / 4);
    int c = idx % (D_MODEL / 4);
    const float4* Y4 = (const float4*)g_Y;
    float4 a = Y4[(size_t)(2 * t + 0) * (D_MODEL / 4) + c];
    float4 b = Y4[(size_t)(2 * t + 1) * (D_MODEL / 4) + c];
    ((float4*)out)[idx] = make_float4(a.x + b.x, a.y + b.y, a.z + b.z, a.w + b.w);
}

extern "C" void kernel_launch(void* const* d_in, const int* in_sizes, int n_in,
                              void* d_out, int out_size) {
    (void)in_sizes; (void)n_in; (void)out_size;
    const float* x    = (const float*)d_in[0];
    const float* Wg   = (const float*)d_in[1];
    const float* bg   = (const float*)d_in[2];
    const float* bias = (const float*)d_in[3];
    const float* W1   = (const float*)d_in[4];
    const float* b1   = (const float*)d_in[5];
    const float* W2   = (const float*)d_in[6];
    const float* b2   = (const float*)d_in[7];
    float* out = (float*)d_out;

    zero_cnt_kernel<<<1, 32>>>();
    gate_kernel<<<NTOK / 8, 256>>>(x, Wg, bg, bias);
    // grid.x = n-tiles (fastest) so expert weights stay L2-resident across m-tiles
    expert_mma<D_MODEL, EXPERT_DIM, true ><<<dim3(EXPERT_DIM / 128, NTOK / 128, NUM_EXPERTS), 256>>>(x, W1, b1);
    expert_mma<EXPERT_DIM, D_MODEL, false><<<dim3(D_MODEL / 128,  NTOK / 128, NUM_EXPERTS), 256>>>(x, W2, b2);
    combine_kernel<<<(NTOK * (D_MODEL / 4) + 255) / 256, 256>>>(out);
}

// round 5
// speedup vs baseline: 2.3647x; 1.1551x over previous
#include <cuda_runtime.h>
#include <stdint.h>
#include <math.h>

#define D_MODEL     1024
#define EXPERT_DIM  2048
#define NUM_EXPERTS 16
#define SEQ_LEN     2048
#define BATCH       2
#define NTOK        (SEQ_LEN*BATCH)      // 4096 tokens
#define NASSIGN     (NTOK*2)             // 8192 (token, k) assignments

// ---- scratch (static __device__: no allocations allowed) ----
__device__ float g_H[(size_t)NASSIGN * EXPERT_DIM];    // 64 MB (stored tf32-exact)
__device__ float g_Y[(size_t)NASSIGN * D_MODEL];       // 32 MB
__device__ float g_Xc[(size_t)NTOK * D_MODEL];         // 16 MB tf32-exact x
__device__ float g_W1c[(size_t)NUM_EXPERTS * D_MODEL * EXPERT_DIM];   // 128 MB
__device__ float g_W2c[(size_t)NUM_EXPERTS * EXPERT_DIM * D_MODEL];   // 128 MB
__device__ int   g_cnt[NUM_EXPERTS];
__device__ int   g_list[NUM_EXPERTS * NTOK];
__device__ float g_rw[NASSIGN];

__device__ __forceinline__ uint32_t f2tf32(float f) {
    uint32_t r;
    asm("cvt.rna.tf32.f32 %0, %1;" : "=r"(r) : "f"(f));
    return r;
}

__global__ void zero_cnt_kernel() {
    if (threadIdx.x < NUM_EXPERTS) g_cnt[threadIdx.x] = 0;
}

// ---- tf32-round a buffer (float4 grid-stride) ----
__global__ void cvt_kernel(const float* __restrict__ in, float* __restrict__ out, int n4) {
    int i = blockIdx.x * blockDim.x + threadIdx.x;
    if (i >= n4) return;
    float4 v = ((const float4*)in)[i];
    float4 o;
    o.x = __uint_as_float(f2tf32(v.x));
    o.y = __uint_as_float(f2tf32(v.y));
    o.z = __uint_as_float(f2tf32(v.z));
    o.w = __uint_as_float(f2tf32(v.w));
    ((float4*)out)[i] = o;
}

// ---- gating: one warp per token (fp32 path, uses raw x) ----
__global__ void gate_kernel(const float* __restrict__ x,
                            const float* __restrict__ Wg,
                            const float* __restrict__ bg,
                            const float* __restrict__ bias) {
    int gwarp = (blockIdx.x * blockDim.x + threadIdx.x) >> 5;
    int lane  = threadIdx.x & 31;
    if (gwarp >= NTOK) return;
    const float* xr = x + (size_t)gwarp * D_MODEL;

    float xv[32];
    #pragma unroll
    for (int j = 0; j < 32; j++) xv[j] = xr[lane + 32 * j];

    float logits[NUM_EXPERTS];
    #pragma unroll
    for (int e = 0; e < NUM_EXPERTS; e++) {
        float s = 0.f;
        #pragma unroll
        for (int j = 0; j < 32; j++)
            s += xv[j] * Wg[(size_t)(lane + 32 * j) * NUM_EXPERTS + e];
        #pragma unroll
        for (int o = 16; o; o >>= 1) s += __shfl_xor_sync(0xffffffffu, s, o);
        logits[e] = s + bg[e] + bias[e];
    }

    if (lane == 0) {
        int e0 = 0; float v0 = logits[0];
        #pragma unroll
        for (int e = 1; e < NUM_EXPERTS; e++)
            if (logits[e] > v0) { v0 = logits[e]; e0 = e; }
        int e1 = -1; float v1 = -1e30f;
        #pragma unroll
        for (int e = 0; e < NUM_EXPERTS; e++)
            if (e != e0 && logits[e] > v1) { v1 = logits[e]; e1 = e; }

        float ew1 = __expf(v1 - v0);
        float inv = 1.f / (1.f + ew1);
        g_rw[gwarp * 2 + 0] = inv;
        g_rw[gwarp * 2 + 1] = ew1 * inv;
        int p0 = atomicAdd(&g_cnt[e0], 1);
        g_list[e0 * NTOK + p0] = gwarp * 2 + 0;
        int p1 = atomicAdd(&g_cnt[e1], 1);
        g_list[e1 * NTOK + p1] = gwarp * 2 + 1;
    }
}

// ================= mma + cp.async helpers =================
__device__ __forceinline__ void mma_tf32(float* d, const uint32_t* a, const uint32_t* b) {
    asm volatile(
        "mma.sync.aligned.m16n8k8.row.col.f32.tf32.tf32.f32 "
        "{%0,%1,%2,%3}, {%4,%5,%6,%7}, {%8,%9}, {%0,%1,%2,%3};\n"
        : "+f"(d[0]), "+f"(d[1]), "+f"(d[2]), "+f"(d[3])
        : "r"(a[0]), "r"(a[1]), "r"(a[2]), "r"(a[3]), "r"(b[0]), "r"(b[1]));
}
__device__ __forceinline__ void cpa16(uint32_t dst, const void* src) {
    asm volatile("cp.async.cg.shared.global [%0], [%1], 16;" :: "r"(dst), "l"(src));
}
#define CPA_COMMIT() asm volatile("cp.async.commit_group;" ::: "memory")
#define CPA_WAIT2()  asm volatile("cp.async.wait_group 2;" ::: "memory")

// smem layout (4-stage pipeline, k16 per stage):
//   s_entry[128]            @ 0      (512 B)
//   A stages: 4 x 10240 B   @ 512     (A[m][k]: 128 rows, stride 20 floats = 80 B)
//   B stages: 4 x 8704  B   @ 41472   (B[k][n]: 16 rows, stride 136 floats = 544 B)
#define SM_A      512
#define SM_ASTG   10240
#define SM_B      41472
#define SM_BSTG   8704
#define SM_TOTAL  76800
#define ASTR      20
#define BSTR      136
#define STAGES    4

template<int K, int N, bool FC1>
__global__ __launch_bounds__(256, 2)
void expert_mma(const float* __restrict__ Abase,
                const float* __restrict__ Wbase,
                const float* __restrict__ BiasBase) {
    extern __shared__ char smem[];
    const int e   = blockIdx.z;
    const int cnt = g_cnt[e];
    const int m0  = blockIdx.y * 128;
    if (m0 >= cnt) return;
    const int n0  = blockIdx.x * 128;

    const float* W  = Wbase    + (size_t)e * K * N;
    const float* bv = BiasBase + (size_t)e * N;

    int* s_entry = (int*)smem;
    const uint32_t sbase = (uint32_t)__cvta_generic_to_shared(smem);

    const int tid = threadIdx.x;
    if (tid < 128) {
        int idx = m0 + tid;
        s_entry[tid] = (idx < cnt) ? g_list[e * NTOK + idx] : -1;
    }
    __syncthreads();

    // ---- producer mappings ----
    // A: thread pair per row: row = tid>>1, two 16B chunks at (tid&1)*8 floats
    const int arow_i = tid >> 1;
    const int acho   = (tid & 1) * 8;           // float offset within k16
    const float* a_src;
    {
        int en = s_entry[arow_i];
        const float* base = FC1 ? g_Xc : g_H;
        size_t stride     = FC1 ? D_MODEL : EXPERT_DIM;
        size_t row        = (en >= 0) ? (size_t)(FC1 ? (en >> 1) : en) : 0;
        a_src = base + row * stride + acho;
    }
    const uint32_t a_dst0 = sbase + SM_A + arow_i * 80 + (tid & 1) * 32;
    // B: kr = tid>>4 (0..15), nq = (tid&15)*2 → two 16B chunks
    const int bkr = tid >> 4;
    const int bnq = (tid & 15) * 2;
    const float* b_src = W + (size_t)bkr * N + n0 + bnq * 4;
    const uint32_t b_dst0 = sbase + SM_B + bkr * 544 + bnq * 16;

    auto produce = [&](int c, int s) {
        int k0 = c * 16;
        uint32_t ao = (uint32_t)(s * SM_ASTG);
        uint32_t bo = (uint32_t)(s * SM_BSTG);
        cpa16(a_dst0 + ao,      a_src + k0);
        cpa16(a_dst0 + ao + 16, a_src + k0 + 4);
        const float* bs = b_src + (size_t)k0 * N;
        cpa16(b_dst0 + bo,      bs);
        cpa16(b_dst0 + bo + 16, bs + 4);
    };

    // ---- consumer mappings (warp tile 32x64, 4m x 2n warps) ----
    const int lane = tid & 31;
    const int wm   = (tid >> 5) & 3;
    const int wn   = tid >> 7;
    const int m0w  = wm * 32;
    const int n0w  = wn * 64;
    const int qr   = lane >> 2;
    const int qc   = lane & 3;

    float acc[2][8][4];
    #pragma unroll
    for (int mi = 0; mi < 2; mi++)
        #pragma unroll
        for (int ni = 0; ni < 8; ni++)
            #pragma unroll
            for (int j = 0; j < 4; j++) acc[mi][ni][j] = 0.f;

    const int nst = K / 16;

    // prologue: fill 3 stages
    produce(0, 0); CPA_COMMIT();
    produce(1, 1); CPA_COMMIT();
    produce(2, 2); CPA_COMMIT();

    for (int c = 0; c < nst; c++) {
        CPA_WAIT2();            // stage c complete (own thread's copies)
        __syncthreads();        // all threads' copies visible; slot (c+3)&3 free
        if (c + 3 < nst) produce(c + 3, (c + 3) & 3);
        CPA_COMMIT();           // keep group counting uniform

        const uint32_t* Ab = (const uint32_t*)(smem + SM_A + (c & 3) * SM_ASTG);
        const uint32_t* Bb = (const uint32_t*)(smem + SM_B + (c & 3) * SM_BSTG);

        #pragma unroll
        for (int kk = 0; kk < 2; kk++) {
            const int kbase = kk * 8 + qc;
            uint32_t afrag[2][4];
            #pragma unroll
            for (int mi = 0; mi < 2; mi++) {
                int r = m0w + mi * 16 + qr;
                afrag[mi][0] = Ab[r * ASTR + kbase];
                afrag[mi][1] = Ab[(r + 8) * ASTR + kbase];
                afrag[mi][2] = Ab[r * ASTR + kbase + 4];
                afrag[mi][3] = Ab[(r + 8) * ASTR + kbase + 4];
            }
            uint32_t bfrag[8][2];
            #pragma unroll
            for (int ni = 0; ni < 8; ni++) {
                int nb = n0w + ni * 8 + qr;
                bfrag[ni][0] = Bb[kbase * BSTR + nb];
                bfrag[ni][1] = Bb[(kbase + 4) * BSTR + nb];
            }
            #pragma unroll
            for (int mi = 0; mi < 2; mi++)
                #pragma unroll
                for (int ni = 0; ni < 8; ni++)
                    mma_tf32(acc[mi][ni], afrag[mi], bfrag[ni]);
        }
    }

    // ---- epilogue ----
    #pragma unroll
    for (int mi = 0; mi < 2; mi++) {
        int r0 = m0w + mi * 16 + qr;
        int r1 = r0 + 8;
        int e0 = s_entry[r0];
        int e1 = s_entry[r1];
        #pragma unroll
        for (int ni = 0; ni < 8; ni++) {
            int ncol = n0 + n0w + ni * 8 + qc * 2;
            float bx = bv[ncol], by = bv[ncol + 1];
            if (FC1) {
                if (e0 >= 0) {
                    float* p = g_H + (size_t)e0 * EXPERT_DIM + ncol;
                    float v0 = acc[mi][ni][0] + bx;
                    float v1 = acc[mi][ni][1] + by;
                    v0 = v0 > 0.f ? v0 : 0.f;
                    v1 = v1 > 0.f ? v1 : 0.f;
                    *(float2*)p = make_float2(__uint_as_float(f2tf32(v0)),
                                              __uint_as_float(f2tf32(v1)));
                }
                if (e1 >= 0) {
                    float* p = g_H + (size_t)e1 * EXPERT_DIM + ncol;
                    float v0 = acc[mi][ni][2] + bx;
                    float v1 = acc[mi][ni][3] + by;
                    v0 = v0 > 0.f ? v0 : 0.f;
                    v1 = v1 > 0.f ? v1 : 0.f;
                    *(float2*)p = make_float2(__uint_as_float(f2tf32(v0)),
                                              __uint_as_float(f2tf32(v1)));
                }
            } else {
                if (e0 >= 0) {
                    float w = g_rw[e0];
                    float* p = g_Y + (size_t)e0 * D_MODEL + ncol;
                    *(float2*)p = make_float2(w * (acc[mi][ni][0] + bx),
                                              w * (acc[mi][ni][1] + by));
                }
                if (e1 >= 0) {
                    float w = g_rw[e1];
                    float* p = g_Y + (size_t)e1 * D_MODEL + ncol;
                    *(float2*)p = make_float2(w * (acc[mi][ni][2] + bx),
                                              w * (acc[mi][ni][3] + by));
                }
            }
        }
    }
}

// ---- combine: out[t] = Y[t, slot0] + Y[t, slot1] ----
__global__ void combine_kernel(float* __restrict__ out) {
    int idx = blockIdx.x * blockDim.x + threadIdx.x;
    if (idx >= NTOK * (D_MODEL / 4)) return;
    int t = idx / (D_MODEL / 4);
    int c = idx % (D_MODEL / 4);
    const float4* Y4 = (const float4*)g_Y;
    float4 a = Y4[(size_t)(2 * t + 0) * (D_MODEL / 4) + c];
    float4 b = Y4[(size_t)(2 * t + 1) * (D_MODEL / 4) + c];
    ((float4*)out)[idx] = make_float4(a.x + b.x, a.y + b.y, a.z + b.z, a.w + b.w);
}

extern "C" void kernel_launch(void* const* d_in, const int* in_sizes, int n_in,
                              void* d_out, int out_size) {
    (void)in_sizes; (void)n_in; (void)out_size;
    const float* x    = (const float*)d_in[0];
    const float* Wg   = (const float*)d_in[1];
    const float* bg   = (const float*)d_in[2];
    const float* bias = (const float*)d_in[3];
    const float* W1   = (const float*)d_in[4];
    const float* b1   = (const float*)d_in[5];
    const float* W2   = (const float*)d_in[6];
    const float* b2   = (const float*)d_in[7];
    float* out = (float*)d_out;

    static int attr_done = 0;
    if (!attr_done) {
        cudaFuncSetAttribute(expert_mma<D_MODEL, EXPERT_DIM, true>,
                             cudaFuncAttributeMaxDynamicSharedMemorySize, SM_TOTAL);
        cudaFuncSetAttribute(expert_mma<EXPERT_DIM, D_MODEL, false>,
                             cudaFuncAttributeMaxDynamicSharedMemorySize, SM_TOTAL);
        attr_done = 1;
    }

    zero_cnt_kernel<<<1, 32>>>();
    gate_kernel<<<NTOK / 8, 256>>>(x, Wg, bg, bias);

    // pre-round operands to tf32-exact fp32 (enables raw cp.async feeding)
    {
        float* xc;  cudaGetSymbolAddress((void**)&xc,  g_Xc);
        float* w1c; cudaGetSymbolAddress((void**)&w1c, g_W1c);
        float* w2c; cudaGetSymbolAddress((void**)&w2c, g_W2c);
        int n4x = NTOK * D_MODEL / 4;
        int n4w = NUM_EXPERTS * D_MODEL * EXPERT_DIM / 4;
        cvt_kernel<<<(n4x + 255) / 256, 256>>>(x,  xc,  n4x);
        cvt_kernel<<<(n4w + 255) / 256, 256>>>(W1, w1c, n4w);
        cvt_kernel<<<(n4w + 255) / 256, 256>>>(W2, w2c, n4w);
    }

    float* w1c; cudaGetSymbolAddress((void**)&w1c, g_W1c);
    float* w2c; cudaGetSymbolAddress((void**)&w2c, g_W2c);

    expert_mma<D_MODEL, EXPERT_DIM, true >
        <<<dim3(EXPERT_DIM / 128, NTOK / 128, NUM_EXPERTS), 256, SM_TOTAL>>>(nullptr, w1c, b1);
    expert_mma<EXPERT_DIM, D_MODEL, false>
        <<<dim3(D_MODEL / 128,  NTOK / 128, NUM_EXPERTS), 256, SM_TOTAL>>>(nullptr, w2c, b2);
    combine_kernel<<<(NTOK * (D_MODEL / 4) + 255) / 256, 256>>>(out);
}